// round 15
// baseline (speedup 1.0000x reference)
#include <cuda_runtime.h>
#include <cuda_bf16.h>

// k-winners-take-all: x (rows=200704, C=256) fp32. Keep x >= 26th largest per row.
// Warp-per-row. Hot path: lean bisection on positive-float bit patterns (prior
// first probe at ~0.59 of bracket) with wide count-exact exits:
//   tot==27 -> 2nd-smallest winner, tot==26 -> min winner,
//   tot==25 -> max loser,           tot==24 -> 2nd-largest loser.
// Bounds via signed REDUX on raw float bits (no key transform).
// Cold path (T<0, ~never on this data, exactness only): 32-step key radix.

constexpr int CHANNELS = 256;
constexpr unsigned KSEL = 26;       // max(1, round(0.1 * 256))
constexpr unsigned FULL = 0xFFFFFFFFu;

__device__ __forceinline__ void ceF(float &a, float &b) {   // a<-max, b<-min
    float hi = fmaxf(a, b), lo = fminf(a, b);
    a = hi; b = lo;
}

__device__ __forceinline__ unsigned f2k(float f) {          // order-preserving key
    unsigned u = __float_as_uint(f);
    unsigned m = (unsigned)((int)u >> 31);
    return u ^ (m | 0x80000000u);
}

__global__ void __launch_bounds__(256)
kwta_kernel(const float* __restrict__ x, float* __restrict__ y, int rows) {
    int gw = (blockIdx.x * blockDim.x + threadIdx.x) >> 5;
    if (gw >= rows) return;
    int lane = threadIdx.x & 31;

    const float4* xp = reinterpret_cast<const float4*>(x) + (size_t)gw * (CHANNELS / 4);
    float4 a = __ldcs(xp + lane);
    float4 b = __ldcs(xp + 32 + lane);

    float f0 = a.x, f1 = a.y, f2 = a.z, f3 = a.w;
    float f4 = b.x, f5 = b.y, f6 = b.z, f7 = b.w;

    // Batcher odd-even mergesort for 8, descending (19 CE)
    ceF(f0,f1); ceF(f2,f3); ceF(f4,f5); ceF(f6,f7);
    ceF(f0,f2); ceF(f1,f3); ceF(f4,f6); ceF(f5,f7);
    ceF(f1,f2); ceF(f5,f6);
    ceF(f0,f4); ceF(f1,f5); ceF(f2,f6); ceF(f3,f7);
    ceF(f2,f4); ceF(f3,f5);
    ceF(f1,f2); ceF(f3,f4); ceF(f5,f6);
    // f0 >= f1 >= ... >= f7

    // per-lane count of {f_j >= c}: branchless binary search on sorted regs
    auto cnt8 = [&](float c) -> unsigned {
        bool c1 = (f3 >= c);
        float t1 = c1 ? f5 : f1;
        bool c2 = (t1 >= c);
        float tA = c2 ? f2 : f0;
        float tB = c2 ? f6 : f4;
        float t2 = c1 ? tB : tA;
        bool c3 = (t2 >= c);
        bool c0 = (f7 >= c);
        return 4u*(unsigned)c1 + 2u*(unsigned)c2 + (unsigned)c3 + (unsigned)c0;
    };

    // Exact threshold when a probe lands at tot in {24,25,26,27}.
    // Hot path only: cf >= 0 and T >= 0; winner patterns order like floats,
    // losers clamped to +0 order like floats. (Zero ties are value-neutral.)
    auto resolveExit = [&](float cf, unsigned tot) -> unsigned {
        const float INF = __int_as_float(0x7F800000);
        if (tot >= KSEL) {
            if (tot == KSEL) {
                // T = min winner: cheap single chain (8 FSEL) + REDUX.MIN
                float t = INF;
                t = (f0 >= cf) ? f0 : t;
                t = (f1 >= cf) ? f1 : t;
                t = (f2 >= cf) ? f2 : t;
                t = (f3 >= cf) ? f3 : t;
                t = (f4 >= cf) ? f4 : t;
                t = (f5 >= cf) ? f5 : t;
                t = (f6 >= cf) ? f6 : t;
                t = (f7 >= cf) ? f7 : t;       // sorted desc: last winner = lane min
                return __reduce_min_sync(FULL, __float_as_uint(t));
            }
            // tot==27: 2nd-smallest winner (two-deep chain + tie ballot)
            float t = INF, u = INF;
            { bool w = (f0 >= cf); u = w ? t : u; t = w ? f0 : t; }
            { bool w = (f1 >= cf); u = w ? t : u; t = w ? f1 : t; }
            { bool w = (f2 >= cf); u = w ? t : u; t = w ? f2 : t; }
            { bool w = (f3 >= cf); u = w ? t : u; t = w ? f3 : t; }
            { bool w = (f4 >= cf); u = w ? t : u; t = w ? f4 : t; }
            { bool w = (f5 >= cf); u = w ? t : u; t = w ? f5 : t; }
            { bool w = (f6 >= cf); u = w ? t : u; t = w ? f6 : t; }
            { bool w = (f7 >= cf); u = w ? t : u; t = w ? f7 : t; }
            unsigned bt = __float_as_uint(t), bu = __float_as_uint(u);
            unsigned m1 = __reduce_min_sync(FULL, bt);
            bool eq = (bt == m1);
            unsigned v  = eq ? bu : bt;
            unsigned m2 = __reduce_min_sync(FULL, v);
            unsigned nt = __popc(__ballot_sync(FULL, eq));
            return (nt > 1u) ? m1 : m2;
        } else {
            if (tot == KSEL - 1u) {
                // T = max loser (>= 0): cheap single chain + REDUX.MAX
                const float NINF = -INF;
                float t = NINF;
                t = (f7 < cf) ? f7 : t;
                t = (f6 < cf) ? f6 : t;
                t = (f5 < cf) ? f5 : t;
                t = (f4 < cf) ? f4 : t;
                t = (f3 < cf) ? f3 : t;
                t = (f2 < cf) ? f2 : t;
                t = (f1 < cf) ? f1 : t;
                t = (f0 < cf) ? f0 : t;        // sorted desc: first loser = lane max
                return __reduce_max_sync(FULL, __float_as_uint(fmaxf(t, 0.0f)));
            }
            // tot==24: 2nd-largest loser
            const float NINF = -INF;
            float t = NINF, u = NINF;
            { bool w = (f7 < cf); u = w ? t : u; t = w ? f7 : t; }
            { bool w = (f6 < cf); u = w ? t : u; t = w ? f6 : t; }
            { bool w = (f5 < cf); u = w ? t : u; t = w ? f5 : t; }
            { bool w = (f4 < cf); u = w ? t : u; t = w ? f4 : t; }
            { bool w = (f3 < cf); u = w ? t : u; t = w ? f3 : t; }
            { bool w = (f2 < cf); u = w ? t : u; t = w ? f2 : t; }
            { bool w = (f1 < cf); u = w ? t : u; t = w ? f1 : t; }
            { bool w = (f0 < cf); u = w ? t : u; t = w ? f0 : t; }
            unsigned bt = __float_as_uint(fmaxf(t, 0.0f));
            unsigned bu = __float_as_uint(fmaxf(u, 0.0f));
            unsigned m1 = __reduce_max_sync(FULL, bt);
            bool eq = (bt == m1);
            unsigned v  = eq ? bu : bt;
            unsigned m2 = __reduce_max_sync(FULL, v);
            unsigned nt = __popc(__ballot_sync(FULL, eq));
            return (nt > 1u) ? m1 : m2;
        }
    };

    // Warp bounds via SIGNED reduction on raw bits of lane max (f0).
    // Valid ordering whenever the result is >= 0 (positive-float patterns).
    int bmax = (int)__float_as_uint(f0);
    int sMin = __reduce_min_sync(FULL, bmax);
    int sMax = __reduce_max_sync(FULL, bmax);

    float thrf;
    bool cold = (sMax < 0);           // warp max < 0 -> T < 0
    bool done = false;
    unsigned thrkey = 0u;
    unsigned lo = 0u;

    if (!cold) {
        unsigned hi = (unsigned)sMax + 1u;        // cnt_ge(hi) == 0 exactly
        if (sMin >= 0) {
            lo = (unsigned)sMin;                  // all lane maxima positive: cnt_ge(lo) >= 32
        } else {
            // some lane max negative: probe at +0.0 (counts all f >= 0)
            unsigned tot0 = __reduce_add_sync(FULL, cnt8(0.0f));
            if (tot0 < KSEL) { cold = true; }
            else if (tot0 <= KSEL + 1u) {         // 26 or 27: resolve right here
                thrkey = resolveExit(0.0f, tot0);
                done = true;
            }                                      // else lo = 0, continue
        }

        if (!cold && !done) {
            if (hi - lo <= 1u) {
                thrkey = lo;
            } else {
                // prior-placed first probe (~0.59 of bracket); bisection after
                unsigned mid = lo + ((hi - lo) >> 5) * 19u;
                if (mid == lo) mid = lo + 1u;

                #pragma unroll 1
                for (;;) {
                    float c = __uint_as_float(mid);
                    unsigned tot = __reduce_add_sync(FULL, cnt8(c));

                    if (tot - (KSEL - 2u) <= 3u) {        // tot in {24,25,26,27}
                        thrkey = resolveExit(c, tot);
                        break;
                    }
                    if (tot > KSEL) lo = mid; else hi = mid;   // tot>=28 / tot<=23
                    if (hi - lo <= 1u) { thrkey = lo; break; } // lo == bits(T)
                    mid = lo + ((hi - lo) >> 1);               // <= 33 iterations
                }
            }
        }
    }

    if (!cold) {
        thrf = __uint_as_float(thrkey);
    } else {
        // ---- COLD: T < 0. Exact 32-step key-domain MSB radix. ----
        unsigned s0 = f2k(f0), s1 = f2k(f1), s2 = f2k(f2), s3 = f2k(f3);
        unsigned s4 = f2k(f4), s5 = f2k(f5), s6 = f2k(f6), s7 = f2k(f7);
        unsigned prefix = 0u;
        #pragma unroll 1
        for (int bit = 31; bit >= 0; --bit) {
            unsigned cand = prefix | (1u << bit);
            unsigned cnt = (unsigned)(s0 >= cand) + (unsigned)(s1 >= cand)
                         + (unsigned)(s2 >= cand) + (unsigned)(s3 >= cand)
                         + (unsigned)(s4 >= cand) + (unsigned)(s5 >= cand)
                         + (unsigned)(s6 >= cand) + (unsigned)(s7 >= cand);
            unsigned tot = __reduce_add_sync(FULL, cnt);
            if (tot >= KSEL) prefix = cand;
        }
        unsigned tu = (prefix & 0x80000000u) ? (prefix ^ 0x80000000u) : ~prefix;
        thrf = __uint_as_float(tu);
    }

    float4 oa, ob;
    oa.x = (a.x >= thrf) ? a.x : 0.0f;
    oa.y = (a.y >= thrf) ? a.y : 0.0f;
    oa.z = (a.z >= thrf) ? a.z : 0.0f;
    oa.w = (a.w >= thrf) ? a.w : 0.0f;
    ob.x = (b.x >= thrf) ? b.x : 0.0f;
    ob.y = (b.y >= thrf) ? b.y : 0.0f;
    ob.z = (b.z >= thrf) ? b.z : 0.0f;
    ob.w = (b.w >= thrf) ? b.w : 0.0f;

    float4* yp = reinterpret_cast<float4*>(y) + (size_t)gw * (CHANNELS / 4);
    __stcs(yp + lane, oa);
    __stcs(yp + 32 + lane, ob);
}

extern "C" void kernel_launch(void* const* d_in, const int* in_sizes, int n_in,
                              void* d_out, int out_size) {
    const float* x = (const float*)d_in[0];
    float* y = (float*)d_out;
    int rows = in_sizes[0] / CHANNELS;            // 200704
    int total_threads = rows * 32;                // one warp per row
    int block = 256;
    int grid = (total_threads + block - 1) / block;
    kwta_kernel<<<grid, block>>>(x, y, rows);
}

// round 17
// speedup vs baseline: 1.0008x; 1.0008x over previous
#include <cuda_runtime.h>
#include <cuda_bf16.h>

// k-winners-take-all: x (rows=200704, C=256) fp32. Keep x >= 26th largest per row.
// Warp-per-row, 128-thread CTAs (4 warps) to minimize warp-retirement quantum.
// Hot path: lean bisection on positive-float bit patterns (prior first probe at
// ~0.59 of bracket) with wide count-exact exits:
//   tot==27 -> 2nd-smallest winner, tot==26 -> min winner,
//   tot==25 -> max loser,           tot==24 -> 2nd-largest loser.
// Cold path (T<0, ~never on this data, exactness only): 32-step key radix.

constexpr int CHANNELS = 256;
constexpr unsigned KSEL = 26;       // max(1, round(0.1 * 256))
constexpr unsigned FULL = 0xFFFFFFFFu;

__device__ __forceinline__ void ceF(float &a, float &b) {   // a<-max, b<-min
    float hi = fmaxf(a, b), lo = fminf(a, b);
    a = hi; b = lo;
}

__device__ __forceinline__ unsigned f2k(float f) {          // order-preserving key
    unsigned u = __float_as_uint(f);
    unsigned m = (unsigned)((int)u >> 31);
    return u ^ (m | 0x80000000u);
}

__global__ void __launch_bounds__(128)
kwta_kernel(const float* __restrict__ x, float* __restrict__ y, int rows) {
    int gw = (blockIdx.x * blockDim.x + threadIdx.x) >> 5;
    if (gw >= rows) return;
    int lane = threadIdx.x & 31;

    const float4* xp = reinterpret_cast<const float4*>(x) + (size_t)gw * (CHANNELS / 4);
    float4 a = __ldcs(xp + lane);
    float4 b = __ldcs(xp + 32 + lane);

    float f0 = a.x, f1 = a.y, f2 = a.z, f3 = a.w;
    float f4 = b.x, f5 = b.y, f6 = b.z, f7 = b.w;

    // Batcher odd-even mergesort for 8, descending (19 CE)
    ceF(f0,f1); ceF(f2,f3); ceF(f4,f5); ceF(f6,f7);
    ceF(f0,f2); ceF(f1,f3); ceF(f4,f6); ceF(f5,f7);
    ceF(f1,f2); ceF(f5,f6);
    ceF(f0,f4); ceF(f1,f5); ceF(f2,f6); ceF(f3,f7);
    ceF(f2,f4); ceF(f3,f5);
    ceF(f1,f2); ceF(f3,f4); ceF(f5,f6);
    // f0 >= f1 >= ... >= f7

    // per-lane count of {f_j >= c}: branchless binary search on sorted regs
    auto cnt8 = [&](float c) -> unsigned {
        bool c1 = (f3 >= c);
        float t1 = c1 ? f5 : f1;
        bool c2 = (t1 >= c);
        float tA = c2 ? f2 : f0;
        float tB = c2 ? f6 : f4;
        float t2 = c1 ? tB : tA;
        bool c3 = (t2 >= c);
        bool c0 = (f7 >= c);
        return 4u*(unsigned)c1 + 2u*(unsigned)c2 + (unsigned)c3 + (unsigned)c0;
    };

    // Exact threshold when a probe lands at tot in {24,25,26,27}.
    // Hot path only: probe cf > float(lo) >= 0 and T >= 0, so winner patterns
    // order like floats; losers clamped to +0 also order like floats.
    auto resolveExit = [&](float cf, unsigned tot) -> unsigned {
        const float INF = __int_as_float(0x7F800000);
        if (tot >= KSEL) {
            float t = INF, u = INF;
            { bool w = (f0 >= cf); u = w ? t : u; t = w ? f0 : t; }
            { bool w = (f1 >= cf); u = w ? t : u; t = w ? f1 : t; }
            { bool w = (f2 >= cf); u = w ? t : u; t = w ? f2 : t; }
            { bool w = (f3 >= cf); u = w ? t : u; t = w ? f3 : t; }
            { bool w = (f4 >= cf); u = w ? t : u; t = w ? f4 : t; }
            { bool w = (f5 >= cf); u = w ? t : u; t = w ? f5 : t; }
            { bool w = (f6 >= cf); u = w ? t : u; t = w ? f6 : t; }
            { bool w = (f7 >= cf); u = w ? t : u; t = w ? f7 : t; }
            unsigned bt = __float_as_uint(t), bu = __float_as_uint(u);
            unsigned m1 = __reduce_min_sync(FULL, bt);      // global min winner
            if (tot == KSEL) return m1;
            bool eq = (bt == m1);
            unsigned v  = eq ? bu : bt;
            unsigned m2 = __reduce_min_sync(FULL, v);
            unsigned nt = __popc(__ballot_sync(FULL, eq));
            return (nt > 1u) ? m1 : m2;
        } else {
            float t = -INF, u = -INF;
            { bool w = (f7 < cf); u = w ? t : u; t = w ? f7 : t; }
            { bool w = (f6 < cf); u = w ? t : u; t = w ? f6 : t; }
            { bool w = (f5 < cf); u = w ? t : u; t = w ? f5 : t; }
            { bool w = (f4 < cf); u = w ? t : u; t = w ? f4 : t; }
            { bool w = (f3 < cf); u = w ? t : u; t = w ? f3 : t; }
            { bool w = (f2 < cf); u = w ? t : u; t = w ? f2 : t; }
            { bool w = (f1 < cf); u = w ? t : u; t = w ? f1 : t; }
            { bool w = (f0 < cf); u = w ? t : u; t = w ? f0 : t; }
            unsigned bt = __float_as_uint(fmaxf(t, 0.0f));
            unsigned bu = __float_as_uint(fmaxf(u, 0.0f));
            unsigned m1 = __reduce_max_sync(FULL, bt);      // global max loser
            if (tot == KSEL - 1u) return m1;
            bool eq = (bt == m1);
            unsigned v  = eq ? bu : bt;
            unsigned m2 = __reduce_max_sync(FULL, v);
            unsigned nt = __popc(__ballot_sync(FULL, eq));
            return (nt > 1u) ? m1 : m2;
        }
    };

    unsigned k0   = f2k(f0);                          // lane-max key
    unsigned keyL = __reduce_min_sync(FULL, k0);      // min lane-max: cnt_ge >= 32
    unsigned keyM = __reduce_max_sync(FULL, k0);      // warp max

    float thrf;
    bool cold = false;
    unsigned lo = 0u;

    if (keyL >= 0x80000000u) {
        lo = keyL ^ 0x80000000u;      // positive pattern; cnt_ge(lo) >= 32 >= KSEL
    } else {
        unsigned cp = __reduce_add_sync(FULL, cnt8(0.0f));
        if (cp < KSEL) cold = true;   // threshold negative
    }

    if (!cold) {
        // ---- HOT: T >= 0, bisection over positive patterns in [lo, hi) ----
        unsigned hi = (keyM ^ 0x80000000u) + 1u;      // cnt_ge(hi) == 0 exactly
        unsigned thrkey;

        if (hi - lo <= 1u) {
            thrkey = lo;
        } else {
            // prior-placed first probe (~0.59 of bracket); pure bisection after
            unsigned mid = lo + ((hi - lo) >> 5) * 19u;
            if (mid == lo) mid = lo + 1u;

            #pragma unroll 1
            for (;;) {
                float c = __uint_as_float(mid);
                unsigned tot = __reduce_add_sync(FULL, cnt8(c));

                if (tot - (KSEL - 2u) <= 3u) {        // tot in {24,25,26,27}
                    thrkey = resolveExit(c, tot);
                    break;
                }
                if (tot > KSEL) lo = mid; else hi = mid;   // tot>=28 / tot<=23
                if (hi - lo <= 1u) { thrkey = lo; break; } // lo == bits(T) exactly
                mid = lo + ((hi - lo) >> 1);               // bisect: <= 33 iters
            }
        }
        thrf = __uint_as_float(thrkey);
    } else {
        // ---- COLD: T < 0. Exact 32-step key-domain MSB radix. ----
        unsigned s0 = f2k(f0), s1 = f2k(f1), s2 = f2k(f2), s3 = f2k(f3);
        unsigned s4 = f2k(f4), s5 = f2k(f5), s6 = f2k(f6), s7 = f2k(f7);
        unsigned prefix = 0u;
        #pragma unroll 1
        for (int bit = 31; bit >= 0; --bit) {
            unsigned cand = prefix | (1u << bit);
            unsigned cnt = (unsigned)(s0 >= cand) + (unsigned)(s1 >= cand)
                         + (unsigned)(s2 >= cand) + (unsigned)(s3 >= cand)
                         + (unsigned)(s4 >= cand) + (unsigned)(s5 >= cand)
                         + (unsigned)(s6 >= cand) + (unsigned)(s7 >= cand);
            unsigned tot = __reduce_add_sync(FULL, cnt);
            if (tot >= KSEL) prefix = cand;
        }
        unsigned tu = (prefix & 0x80000000u) ? (prefix ^ 0x80000000u) : ~prefix;
        thrf = __uint_as_float(tu);
    }

    float4 oa, ob;
    oa.x = (a.x >= thrf) ? a.x : 0.0f;
    oa.y = (a.y >= thrf) ? a.y : 0.0f;
    oa.z = (a.z >= thrf) ? a.z : 0.0f;
    oa.w = (a.w >= thrf) ? a.w : 0.0f;
    ob.x = (b.x >= thrf) ? b.x : 0.0f;
    ob.y = (b.y >= thrf) ? b.y : 0.0f;
    ob.z = (b.z >= thrf) ? b.z : 0.0f;
    ob.w = (b.w >= thrf) ? b.w : 0.0f;

    float4* yp = reinterpret_cast<float4*>(y) + (size_t)gw * (CHANNELS / 4);
    __stcs(yp + lane, oa);
    __stcs(yp + 32 + lane, ob);
}

extern "C" void kernel_launch(void* const* d_in, const int* in_sizes, int n_in,
                              void* d_out, int out_size) {
    const float* x = (const float*)d_in[0];
    float* y = (float*)d_out;
    int rows = in_sizes[0] / CHANNELS;            // 200704
    int total_threads = rows * 32;                // one warp per row
    int block = 128;                               // 4-warp CTAs: finer retirement
    int grid = (total_threads + block - 1) / block;
    kwta_kernel<<<grid, block>>>(x, y, rows);
}